// round 10
// baseline (speedup 1.0000x reference)
#include <cuda_runtime.h>
#include <cuda_fp16.h>
#include <mma.h>
#include <cstdint>

using namespace nvcuda;

#define N_NODES 100000
#define N_EDGES 1600000
#define F_IN    128
#define F_HID   64
#define F_OUT   40

#define SCAN_T  1024
#define SCAN_NB ((N_NODES + SCAN_T - 1) / SCAN_T)   // 98

// ---------------- scratch (static device globals; no allocation) ----------------
__device__ int    g_degs_i[N_NODES];
__device__ int    g_degd_i[N_NODES];
__device__ float  g_ns[N_NODES];
__device__ float  g_nd[N_NODES];
__device__ int    g_incl[N_NODES];
__device__ int    g_rowoff[N_NODES + 1];
__device__ int    g_cursor[N_NODES];
__device__ int    g_partial[SCAN_NB];
__device__ int    g_csrc[N_EDGES];
__device__ __half g_xw64[(size_t)N_NODES * F_HID];
__device__ __half g_xw40[(size_t)N_NODES * F_OUT];
__device__ __half g_agg [(size_t)N_NODES * F_HID];

// ---------------- zero both degree arrays (int4) ----------------
__global__ void k_zero_deg() {
    int i = blockIdx.x * blockDim.x + threadIdx.x;
    if (i < N_NODES / 4) {
        ((int4*)g_degs_i)[i] = make_int4(0, 0, 0, 0);
        ((int4*)g_degd_i)[i] = make_int4(0, 0, 0, 0);
    }
}

// ---------------- degree histograms (4 edges per thread) ----------------
__global__ void k_deg_dst(const int* __restrict__ dst) {
    int i = blockIdx.x * blockDim.x + threadIdx.x;
    if (i < N_EDGES / 4) {
        const int4 d = __ldg(&((const int4*)dst)[i]);
        atomicAdd(&g_degd_i[d.x], 1);
        atomicAdd(&g_degd_i[d.y], 1);
        atomicAdd(&g_degd_i[d.z], 1);
        atomicAdd(&g_degd_i[d.w], 1);
    }
}

__global__ void k_deg_src(const int* __restrict__ src) {
    int i = blockIdx.x * blockDim.x + threadIdx.x;
    if (i < N_EDGES / 4) {
        const int4 s = __ldg(&((const int4*)src)[i]);
        atomicAdd(&g_degs_i[s.x], 1);
        atomicAdd(&g_degs_i[s.y], 1);
        atomicAdd(&g_degs_i[s.z], 1);
        atomicAdd(&g_degs_i[s.w], 1);
    }
}

__global__ void k_ns() {
    int i = blockIdx.x * blockDim.x + threadIdx.x;
    if (i < N_NODES) g_ns[i] = rsqrtf(fmaxf((float)g_degs_i[i], 1.0f));
}

// ---------------- CSR build ----------------
__global__ __launch_bounds__(SCAN_T) void k_scan_block() {
    __shared__ int ws[32];
    int g = blockIdx.x * SCAN_T + threadIdx.x;
    int lane = threadIdx.x & 31, wid = threadIdx.x >> 5;
    int x = (g < N_NODES) ? g_degd_i[g] : 0;
#pragma unroll
    for (int o = 1; o < 32; o <<= 1) {
        int y = __shfl_up_sync(0xFFFFFFFFu, x, o);
        if (lane >= o) x += y;
    }
    if (lane == 31) ws[wid] = x;
    __syncthreads();
    if (wid == 0) {
        int y = ws[lane];
#pragma unroll
        for (int o = 1; o < 32; o <<= 1) {
            int z = __shfl_up_sync(0xFFFFFFFFu, y, o);
            if (lane >= o) y += z;
        }
        ws[lane] = y;
    }
    __syncthreads();
    int incl = x + (wid > 0 ? ws[wid - 1] : 0);
    if (g < N_NODES) g_incl[g] = incl;
    if (threadIdx.x == SCAN_T - 1) g_partial[blockIdx.x] = incl;
}

__global__ __launch_bounds__(SCAN_T) void k_finalize() {
    __shared__ int ws[32];
    __shared__ int s_off;
    const int tid = threadIdx.x;
    const int lane = tid & 31, w = tid >> 5;

    int v = 0;
    if (tid < SCAN_NB && tid < blockIdx.x) v = g_partial[tid];
#pragma unroll
    for (int o = 16; o > 0; o >>= 1) v += __shfl_down_sync(0xFFFFFFFFu, v, o);
    if (tid < 128 && lane == 0) ws[w] = v;
    __syncthreads();
    if (tid == 0) s_off = ws[0] + ws[1] + ws[2] + ws[3];
    __syncthreads();
    const int off = s_off;

    int g = blockIdx.x * SCAN_T + tid;
    if (g < N_NODES) {
        int dd   = g_degd_i[g];
        int incl = g_incl[g] + off;
        g_rowoff[g + 1] = incl;
        g_cursor[g] = incl - dd;
        if (g == 0) g_rowoff[0] = 0;
        g_nd[g] = rsqrtf(fmaxf((float)dd, 1.0f));
    }
}

__global__ void k_fill(const int* __restrict__ src, const int* __restrict__ dst) {
    int i = blockIdx.x * blockDim.x + threadIdx.x;
    if (i < N_EDGES / 4) {
        const int4 s = __ldg(&((const int4*)src)[i]);
        const int4 d = __ldg(&((const int4*)dst)[i]);
        g_csrc[atomicAdd(&g_cursor[d.x], 1)] = s.x;
        g_csrc[atomicAdd(&g_cursor[d.y], 1)] = s.y;
        g_csrc[atomicAdd(&g_cursor[d.z], 1)] = s.z;
        g_csrc[atomicAdd(&g_cursor[d.w], 1)] = s.w;
    }
}

// ---------------- 8-wide loaders for the wmma A tile ----------------
__device__ __forceinline__ void load8(const float* p, float* v) {
    const float4 a = *(const float4*)p;
    const float4 b = *(const float4*)(p + 4);
    v[0] = a.x; v[1] = a.y; v[2] = a.z; v[3] = a.w;
    v[4] = b.x; v[5] = b.y; v[6] = b.z; v[7] = b.w;
}
__device__ __forceinline__ void load8(const __half* p, float* v) {
    union { uint4 u; __half2 h[4]; } r;
    r.u = *(const uint4*)p;
#pragma unroll
    for (int j = 0; j < 4; j++) {
        const float2 t = __half22float2(r.h[j]);
        v[2 * j + 0] = t.x;
        v[2 * j + 1] = t.y;
    }
}

// ---------------- HMMA (wmma) GEMM: Y[N,M] = op(X)[N,K] @ W[K,M] -> fp16 ----------------
// Block tile 128x64, 8 warps; warp w owns rows [w*16, w*16+16) x 64 cols.
// PRE: x' = relu(x * g_nd[row] + bpre[k]) applied during A-tile load (fp32, then fp16).
// SNS: y = acc * g_ns[row] applied in the fp32 epilogue before the fp16 store.
template <int K, int M, bool PRE, bool SNS, typename TX>
__global__ __launch_bounds__(256) void k_gemm_mma(const TX* __restrict__ X,
                                                  const float* __restrict__ W,
                                                  __half* __restrict__ Y,
                                                  const float* __restrict__ bpre) {
    __shared__ __align__(16) __half As[128][16];
    __shared__ __align__(16) __half Bs[16][64];
    __shared__ __align__(16) float  Cs[8][16][64];   // per-warp staging

    const int tid  = threadIdx.x;
    const int warp = tid >> 5;
    const int lane = tid & 31;
    const int row0 = blockIdx.x * 128;

    // A-load role: thread t -> row (t>>1), k-half (t&1)*8
    const int ar   = tid >> 1;
    const int ak   = (tid & 1) * 8;
    const int lrow = row0 + ar;
    const bool lok = (lrow < N_NODES);

    float ndv = 0.0f;
    if (PRE) ndv = lok ? g_nd[lrow] : 0.0f;

    // B-load role: thread t -> k-row (t>>4), col (t&15)*4
    const int bk = tid >> 4;
    const int bc = (tid & 15) * 4;

    wmma::fragment<wmma::accumulator, 16, 16, 16, float> cf[4];
#pragma unroll
    for (int n = 0; n < 4; n++) wmma::fill_fragment(cf[n], 0.0f);

    for (int kc = 0; kc < K; kc += 16) {
        // ---- A tile: 128 rows x 16 k, convert to fp16 (+ PRE) ----
        {
            float v[8] = {0.f, 0.f, 0.f, 0.f, 0.f, 0.f, 0.f, 0.f};
            if (lok) load8(&X[(size_t)lrow * K + kc + ak], v);
            if (PRE) {
#pragma unroll
                for (int j = 0; j < 8; j++)
                    v[j] = fmaxf(fmaf(v[j], ndv, __ldg(&bpre[kc + ak + j])), 0.f);
            }
            union { uint4 u; __half2 h[4]; } p;
#pragma unroll
            for (int j = 0; j < 4; j++)
                p.h[j] = __floats2half2_rn(v[2 * j], v[2 * j + 1]);
            *(uint4*)&As[ar][ak] = p.u;
        }
        // ---- B tile: 16 k x 64 cols fp32 W -> fp16 (zero-pad past M) ----
        {
            float4 wv = make_float4(0.f, 0.f, 0.f, 0.f);
            if (bc < M)
                wv = *(const float4*)&W[(size_t)(kc + bk) * M + bc];
            union { uint2 u; __half2 h[2]; } p;
            p.h[0] = __floats2half2_rn(wv.x, wv.y);
            p.h[1] = __floats2half2_rn(wv.z, wv.w);
            *(uint2*)&Bs[bk][bc] = p.u;
        }
        __syncthreads();

        wmma::fragment<wmma::matrix_a, 16, 16, 16, __half, wmma::row_major> af;
        wmma::load_matrix_sync(af, &As[warp * 16][0], 16);
#pragma unroll
        for (int n = 0; n < 4; n++) {
            wmma::fragment<wmma::matrix_b, 16, 16, 16, __half, wmma::row_major> bf;
            wmma::load_matrix_sync(bf, &Bs[0][n * 16], 64);
            wmma::mma_sync(cf[n], af, bf, cf[n]);
        }
        __syncthreads();
    }

    // ---- epilogue: stage fp32, scale by ns, convert fp16, store ----
#pragma unroll
    for (int n = 0; n < 4; n++)
        wmma::store_matrix_sync(&Cs[warp][0][n * 16], cf[n], 64, wmma::mem_row_major);
    __syncwarp();

    // 16 rows x 16 quads = 256 quads, 8 per lane
    for (int q = lane; q < 256; q += 32) {
        const int r  = q >> 4;
        const int qc = (q & 15) * 4;
        const int rr = row0 + warp * 16 + r;
        if (rr < N_NODES && qc < M) {
            const float s = SNS ? g_ns[rr] : 1.0f;
            union { uint2 u; __half2 h[2]; } p;
            p.h[0] = __floats2half2_rn(Cs[warp][r][qc + 0] * s, Cs[warp][r][qc + 1] * s);
            p.h[1] = __floats2half2_rn(Cs[warp][r][qc + 2] * s, Cs[warp][r][qc + 3] * s);
            *(uint2*)&Y[(size_t)rr * M + qc] = p.u;
        }
    }
}

// ---------------- CSR gather (fp16 in/out, fp32 accum): 8 thr/node, 16B loads ----------------
__device__ __forceinline__ void h8_acc(float* acc, uint4 raw) {
    union { uint4 u; __half2 h[4]; } p; p.u = raw;
#pragma unroll
    for (int j = 0; j < 4; j++) {
        const float2 v = __half22float2(p.h[j]);
        acc[2 * j + 0] += v.x;
        acc[2 * j + 1] += v.y;
    }
}

__global__ __launch_bounds__(256) void k_gather64(const __half* __restrict__ xw,
                                                  __half* __restrict__ agg) {
    const int node = blockIdx.x * 32 + (threadIdx.x >> 3);
    if (node >= N_NODES) return;
    const int f   = (threadIdx.x & 7) << 3;
    int       i   = g_rowoff[node];
    const int end = g_rowoff[node + 1];
    float acc[8] = {0.f, 0.f, 0.f, 0.f, 0.f, 0.f, 0.f, 0.f};

    for (; i + 3 < end; i += 4) {
        const int s0 = __ldg(&g_csrc[i + 0]);
        const int s1 = __ldg(&g_csrc[i + 1]);
        const int s2 = __ldg(&g_csrc[i + 2]);
        const int s3 = __ldg(&g_csrc[i + 3]);
        const uint4 r0 = __ldg((const uint4*)&xw[(size_t)s0 * 64 + f]);
        const uint4 r1 = __ldg((const uint4*)&xw[(size_t)s1 * 64 + f]);
        const uint4 r2 = __ldg((const uint4*)&xw[(size_t)s2 * 64 + f]);
        const uint4 r3 = __ldg((const uint4*)&xw[(size_t)s3 * 64 + f]);
        h8_acc(acc, r0); h8_acc(acc, r1);
        h8_acc(acc, r2); h8_acc(acc, r3);
    }
    for (; i < end; i++) {
        const int s = __ldg(&g_csrc[i]);
        h8_acc(acc, __ldg((const uint4*)&xw[(size_t)s * 64 + f]));
    }

    union { uint4 u; __half2 h[4]; } o;
    o.h[0] = __floats2half2_rn(acc[0], acc[1]);
    o.h[1] = __floats2half2_rn(acc[2], acc[3]);
    o.h[2] = __floats2half2_rn(acc[4], acc[5]);
    o.h[3] = __floats2half2_rn(acc[6], acc[7]);
    *(uint4*)&agg[(size_t)node * 64 + f] = o.u;
}

// 40-wide fp16 gather with fused final epilogue (fp32 output)
__device__ __forceinline__ void h4_acc(float4& acc, uint2 raw) {
    union { uint2 u; __half2 h[2]; } p; p.u = raw;
    const float2 a = __half22float2(p.h[0]);
    const float2 b = __half22float2(p.h[1]);
    acc.x += a.x; acc.y += a.y; acc.z += b.x; acc.w += b.y;
}

__global__ __launch_bounds__(256) void k_gather40(const __half* __restrict__ xw,
                                                  float* __restrict__ out,
                                                  const float* __restrict__ b2) {
    const int node = blockIdx.x * 16 + (threadIdx.x >> 4);
    if (node >= N_NODES) return;
    const int f = (threadIdx.x & 15) << 2;
    if (f >= F_OUT) return;
    int       i   = g_rowoff[node];
    const int end = g_rowoff[node + 1];
    float4 acc = make_float4(0.f, 0.f, 0.f, 0.f);
    for (; i + 3 < end; i += 4) {
        const int s0 = __ldg(&g_csrc[i + 0]);
        const int s1 = __ldg(&g_csrc[i + 1]);
        const int s2 = __ldg(&g_csrc[i + 2]);
        const int s3 = __ldg(&g_csrc[i + 3]);
        h4_acc(acc, __ldg((const uint2*)&xw[(size_t)s0 * F_OUT + f]));
        h4_acc(acc, __ldg((const uint2*)&xw[(size_t)s1 * F_OUT + f]));
        h4_acc(acc, __ldg((const uint2*)&xw[(size_t)s2 * F_OUT + f]));
        h4_acc(acc, __ldg((const uint2*)&xw[(size_t)s3 * F_OUT + f]));
    }
    for (; i < end; i++) {
        const int s = __ldg(&g_csrc[i]);
        h4_acc(acc, __ldg((const uint2*)&xw[(size_t)s * F_OUT + f]));
    }
    const float nd = g_nd[node];
    float4 o;
    o.x = fmaf(acc.x, nd, __ldg(&b2[f + 0]));
    o.y = fmaf(acc.y, nd, __ldg(&b2[f + 1]));
    o.z = fmaf(acc.z, nd, __ldg(&b2[f + 2]));
    o.w = fmaf(acc.w, nd, __ldg(&b2[f + 3]));
    *(float4*)&out[(size_t)node * F_OUT + f] = o;
}

// ---------------- host launch ----------------
extern "C" void kernel_launch(void* const* d_in, const int* in_sizes, int n_in,
                              void* d_out, int out_size) {
    (void)in_sizes; (void)n_in; (void)out_size;
    const float* h   = (const float*)d_in[0];
    const float* W0  = (const float*)d_in[1];
    const float* b0  = (const float*)d_in[2];
    const float* W1  = (const float*)d_in[3];
    const float* b1  = (const float*)d_in[4];
    const float* W2  = (const float*)d_in[5];
    const float* b2  = (const float*)d_in[6];
    const int*   src = (const int*)d_in[7];
    const int*   dst = (const int*)d_in[8];
    float* out = (float*)d_out;

    __half *pXW64, *pXW40, *pAgg;
    cudaGetSymbolAddress((void**)&pXW64, g_xw64);
    cudaGetSymbolAddress((void**)&pXW40, g_xw40);
    cudaGetSymbolAddress((void**)&pAgg,  g_agg);

    static cudaStream_t s2 = []() {
        cudaStream_t s; cudaStreamCreateWithFlags(&s, cudaStreamNonBlocking); return s;
    }();
    static cudaEvent_t evFork = []() {
        cudaEvent_t e; cudaEventCreateWithFlags(&e, cudaEventDisableTiming); return e;
    }();
    static cudaEvent_t evJoin = []() {
        cudaEvent_t e; cudaEventCreateWithFlags(&e, cudaEventDisableTiming); return e;
    }();

    const int nodeBlocks   = (N_NODES + 255) / 256;
    const int edge4Blocks  = (N_EDGES / 4 + 255) / 256;
    const int gemmBlocks   = (N_NODES + 127) / 128;
    const int gath64Blocks = (N_NODES + 31) / 32;
    const int gath40Blocks = (N_NODES + 15) / 16;

    // ---- main: zero degrees, then fork ----
    k_zero_deg<<<(N_NODES / 4 + 255) / 256, 256>>>();
    cudaEventRecord(evFork, 0);

    // ---- side stream: src-degree -> ns -> GEMM0 (ns folded into epilogue) ----
    cudaStreamWaitEvent(s2, evFork, 0);
    k_deg_src<<<edge4Blocks, 256, 0, s2>>>(src);
    k_ns<<<nodeBlocks, 256, 0, s2>>>();
    k_gemm_mma<F_IN, F_HID, false, true><<<gemmBlocks, 256, 0, s2>>>(h, W0, pXW64, b0);
    cudaEventRecord(evJoin, s2);

    // ---- main: dst histogram + CSR ----
    k_deg_dst<<<edge4Blocks, 256>>>(dst);
    k_scan_block<<<SCAN_NB, SCAN_T>>>();
    k_finalize<<<SCAN_NB, SCAN_T>>>();
    k_fill<<<edge4Blocks, 256>>>(src, dst);

    // ---- join, then the serial back chain ----
    cudaStreamWaitEvent(0, evJoin, 0);
    k_gather64<<<gath64Blocks, 256>>>(pXW64, pAgg);

    k_gemm_mma<F_HID, F_HID, true, true><<<gemmBlocks, 256>>>(pAgg, W1, pXW64, b0);
    k_gather64<<<gath64Blocks, 256>>>(pXW64, pAgg);

    k_gemm_mma<F_HID, F_OUT, true, true><<<gemmBlocks, 256>>>(pAgg, W2, pXW40, b1);
    k_gather40<<<gath40Blocks, 256>>>(pXW40, out, b2);
}

// round 11
// speedup vs baseline: 1.0761x; 1.0761x over previous
#include <cuda_runtime.h>
#include <cuda_fp16.h>
#include <mma.h>
#include <cstdint>

using namespace nvcuda;

#define N_NODES 100000
#define N_EDGES 1600000
#define F_IN    128
#define F_HID   64
#define F_OUT   40

#define SCAN_T  1024
#define SCAN_NB ((N_NODES + SCAN_T - 1) / SCAN_T)   // 98

// ---------------- scratch (static device globals; no allocation) ----------------
__device__ int    g_degs_i[N_NODES];
__device__ int    g_degd_i[N_NODES];
__device__ float  g_ns[N_NODES];
__device__ float  g_nd[N_NODES];
__device__ int    g_incl[N_NODES];
__device__ int    g_rowoff[N_NODES + 1];
__device__ int    g_cursor[N_NODES];
__device__ int    g_partial[SCAN_NB];
__device__ int    g_csrc[N_EDGES];
__device__ __half g_xw64[(size_t)N_NODES * F_HID];
__device__ __half g_xw40[(size_t)N_NODES * F_OUT];
__device__ __half g_agg [(size_t)N_NODES * F_HID];

// ---------------- zero both degree arrays (int4) ----------------
__global__ void k_zero_deg() {
    int i = blockIdx.x * blockDim.x + threadIdx.x;
    if (i < N_NODES / 4) {
        ((int4*)g_degs_i)[i] = make_int4(0, 0, 0, 0);
        ((int4*)g_degd_i)[i] = make_int4(0, 0, 0, 0);
    }
}

// ---------------- degree histograms (4 edges per thread) ----------------
__global__ void k_deg_dst(const int* __restrict__ dst) {
    int i = blockIdx.x * blockDim.x + threadIdx.x;
    if (i < N_EDGES / 4) {
        const int4 d = __ldg(&((const int4*)dst)[i]);
        atomicAdd(&g_degd_i[d.x], 1);
        atomicAdd(&g_degd_i[d.y], 1);
        atomicAdd(&g_degd_i[d.z], 1);
        atomicAdd(&g_degd_i[d.w], 1);
    }
}

__global__ void k_deg_src(const int* __restrict__ src) {
    int i = blockIdx.x * blockDim.x + threadIdx.x;
    if (i < N_EDGES / 4) {
        const int4 s = __ldg(&((const int4*)src)[i]);
        atomicAdd(&g_degs_i[s.x], 1);
        atomicAdd(&g_degs_i[s.y], 1);
        atomicAdd(&g_degs_i[s.z], 1);
        atomicAdd(&g_degs_i[s.w], 1);
    }
}

__global__ void k_ns() {
    int i = blockIdx.x * blockDim.x + threadIdx.x;
    if (i < N_NODES) g_ns[i] = rsqrtf(fmaxf((float)g_degs_i[i], 1.0f));
}

// ---------------- CSR build ----------------
__global__ __launch_bounds__(SCAN_T) void k_scan_block() {
    __shared__ int ws[32];
    int g = blockIdx.x * SCAN_T + threadIdx.x;
    int lane = threadIdx.x & 31, wid = threadIdx.x >> 5;
    int x = (g < N_NODES) ? g_degd_i[g] : 0;
#pragma unroll
    for (int o = 1; o < 32; o <<= 1) {
        int y = __shfl_up_sync(0xFFFFFFFFu, x, o);
        if (lane >= o) x += y;
    }
    if (lane == 31) ws[wid] = x;
    __syncthreads();
    if (wid == 0) {
        int y = ws[lane];
#pragma unroll
        for (int o = 1; o < 32; o <<= 1) {
            int z = __shfl_up_sync(0xFFFFFFFFu, y, o);
            if (lane >= o) y += z;
        }
        ws[lane] = y;
    }
    __syncthreads();
    int incl = x + (wid > 0 ? ws[wid - 1] : 0);
    if (g < N_NODES) g_incl[g] = incl;
    if (threadIdx.x == SCAN_T - 1) g_partial[blockIdx.x] = incl;
}

__global__ __launch_bounds__(SCAN_T) void k_finalize() {
    __shared__ int ws[32];
    __shared__ int s_off;
    const int tid = threadIdx.x;
    const int lane = tid & 31, w = tid >> 5;

    int v = 0;
    if (tid < SCAN_NB && tid < blockIdx.x) v = g_partial[tid];
#pragma unroll
    for (int o = 16; o > 0; o >>= 1) v += __shfl_down_sync(0xFFFFFFFFu, v, o);
    if (tid < 128 && lane == 0) ws[w] = v;
    __syncthreads();
    if (tid == 0) s_off = ws[0] + ws[1] + ws[2] + ws[3];
    __syncthreads();
    const int off = s_off;

    int g = blockIdx.x * SCAN_T + tid;
    if (g < N_NODES) {
        int dd   = g_degd_i[g];
        int incl = g_incl[g] + off;
        g_rowoff[g + 1] = incl;
        g_cursor[g] = incl - dd;
        if (g == 0) g_rowoff[0] = 0;
        g_nd[g] = rsqrtf(fmaxf((float)dd, 1.0f));
    }
}

__global__ void k_fill(const int* __restrict__ src, const int* __restrict__ dst) {
    int i = blockIdx.x * blockDim.x + threadIdx.x;
    if (i < N_EDGES / 4) {
        const int4 s = __ldg(&((const int4*)src)[i]);
        const int4 d = __ldg(&((const int4*)dst)[i]);
        g_csrc[atomicAdd(&g_cursor[d.x], 1)] = s.x;
        g_csrc[atomicAdd(&g_cursor[d.y], 1)] = s.y;
        g_csrc[atomicAdd(&g_cursor[d.z], 1)] = s.z;
        g_csrc[atomicAdd(&g_cursor[d.w], 1)] = s.w;
    }
}

// ---------------- 8-wide loaders for the wmma A tile ----------------
__device__ __forceinline__ void load8(const float* p, float* v) {
    const float4 a = *(const float4*)p;
    const float4 b = *(const float4*)(p + 4);
    v[0] = a.x; v[1] = a.y; v[2] = a.z; v[3] = a.w;
    v[4] = b.x; v[5] = b.y; v[6] = b.z; v[7] = b.w;
}
__device__ __forceinline__ void load8(const __half* p, float* v) {
    union { uint4 u; __half2 h[4]; } r;
    r.u = *(const uint4*)p;
#pragma unroll
    for (int j = 0; j < 4; j++) {
        const float2 t = __half22float2(r.h[j]);
        v[2 * j + 0] = t.x;
        v[2 * j + 1] = t.y;
    }
}

// ---------------- HMMA (wmma) GEMM, single-K-pass: Y = op(X) @ W -> fp16 ----------------
// Block tile 128 rows x 64 cols, 8 warps (warp owns 16 rows).
// Whole K staged in padded fp16 smem with MLP=8 loads; exactly 2 __syncthreads.
// PRE: x' = relu(x * g_nd[row] + bpre[k]).  SNS: y = acc * g_ns[row].
template <int K, int M, bool PRE, bool SNS, typename TX>
__global__ __launch_bounds__(256) void k_gemm_mma(const TX* __restrict__ X,
                                                  const float* __restrict__ W,
                                                  __half* __restrict__ Y,
                                                  const float* __restrict__ bpre) {
    static constexpr int AL = K + 8;     // padded A ld (halves)
    static constexpr int BL = 72;        // padded B ld (halves)
    static constexpr int A_BYTES = 128 * AL * 2;
    static constexpr int B_BYTES = K * BL * 2;
    static constexpr int STAGE_BYTES = 8 * 16 * 64 * 4;   // 32 KB fp32 epilogue staging
    static constexpr int SMEM_BYTES =
        (A_BYTES + B_BYTES) > STAGE_BYTES ? (A_BYTES + B_BYTES) : STAGE_BYTES;

    __shared__ __align__(16) char smem[SMEM_BYTES];
    __half* As = (__half*)smem;                  // [128][AL]
    __half* Bs = (__half*)(smem + A_BYTES);      // [K][BL]
    float*  Cs = (float*)smem;                   // reused after sync: [8][16][64]

    const int tid  = threadIdx.x;
    const int warp = tid >> 5;
    const int lane = tid & 31;
    const int row0 = blockIdx.x * 128;

    // ---- A load: 2 threads per row, K/2 contiguous elems each, 8 at a time ----
    const int ar    = tid >> 1;
    const int ah    = (tid & 1) * (K / 2);
    const int lrow  = row0 + ar;
    const bool lok  = (lrow < N_NODES);
    float ndv = 0.0f;
    if (PRE) ndv = lok ? g_nd[lrow] : 0.0f;

#pragma unroll
    for (int j0 = 0; j0 < K / 2; j0 += 8) {
        const int k = ah + j0;
        float v[8] = {0.f, 0.f, 0.f, 0.f, 0.f, 0.f, 0.f, 0.f};
        if (lok) load8(&X[(size_t)lrow * K + k], v);
        if (PRE) {
#pragma unroll
            for (int j = 0; j < 8; j++)
                v[j] = fmaxf(fmaf(v[j], ndv, __ldg(&bpre[k + j])), 0.f);
        }
        union { uint4 u; __half2 h[4]; } p;
#pragma unroll
        for (int j = 0; j < 4; j++)
            p.h[j] = __floats2half2_rn(v[2 * j], v[2 * j + 1]);
        *(uint4*)&As[ar * AL + k] = p.u;
    }

    // ---- B load: K x 64 cols (fp32 W -> fp16, zero-pad past M) ----
#pragma unroll
    for (int i = 0; i < K / 16; i++) {
        const int q    = i * 256 + tid;
        const int brow = q >> 4;
        const int bcol = (q & 15) * 4;
        float4 wv = make_float4(0.f, 0.f, 0.f, 0.f);
        if (bcol < M)
            wv = *(const float4*)&W[(size_t)brow * M + bcol];
        union { uint2 u; __half2 h[2]; } p;
        p.h[0] = __floats2half2_rn(wv.x, wv.y);
        p.h[1] = __floats2half2_rn(wv.z, wv.w);
        *(uint2*)&Bs[brow * BL + bcol] = p.u;
    }
    __syncthreads();

    // ---- all MMAs back-to-back ----
    wmma::fragment<wmma::accumulator, 16, 16, 16, float> cf[4];
#pragma unroll
    for (int n = 0; n < 4; n++) wmma::fill_fragment(cf[n], 0.0f);

#pragma unroll
    for (int kc = 0; kc < K; kc += 16) {
        wmma::fragment<wmma::matrix_a, 16, 16, 16, __half, wmma::row_major> af;
        wmma::load_matrix_sync(af, &As[(warp * 16) * AL + kc], AL);
#pragma unroll
        for (int n = 0; n < 4; n++) {
            wmma::fragment<wmma::matrix_b, 16, 16, 16, __half, wmma::row_major> bf;
            wmma::load_matrix_sync(bf, &Bs[kc * BL + n * 16], BL);
            wmma::mma_sync(cf[n], af, bf, cf[n]);
        }
    }
    __syncthreads();   // A/B smem dead; reuse as fp32 staging

    // ---- epilogue: stage fp32, scale by ns, convert fp16, store ----
    float* cwarp = Cs + warp * (16 * 64);
#pragma unroll
    for (int n = 0; n < 4; n++)
        wmma::store_matrix_sync(cwarp + n * 16, cf[n], 64, wmma::mem_row_major);
    __syncwarp();

    for (int q = lane; q < 256; q += 32) {
        const int r  = q >> 4;
        const int qc = (q & 15) * 4;
        const int rr = row0 + warp * 16 + r;
        if (rr < N_NODES && qc < M) {
            const float s = SNS ? g_ns[rr] : 1.0f;
            union { uint2 u; __half2 h[2]; } p;
            p.h[0] = __floats2half2_rn(cwarp[r * 64 + qc + 0] * s, cwarp[r * 64 + qc + 1] * s);
            p.h[1] = __floats2half2_rn(cwarp[r * 64 + qc + 2] * s, cwarp[r * 64 + qc + 3] * s);
            *(uint2*)&Y[(size_t)rr * M + qc] = p.u;
        }
    }
}

// ---------------- CSR gather (fp16 in/out, fp32 accum): 8 thr/node, 16B loads ----------------
__device__ __forceinline__ void h8_acc(float* acc, uint4 raw) {
    union { uint4 u; __half2 h[4]; } p; p.u = raw;
#pragma unroll
    for (int j = 0; j < 4; j++) {
        const float2 v = __half22float2(p.h[j]);
        acc[2 * j + 0] += v.x;
        acc[2 * j + 1] += v.y;
    }
}

__global__ __launch_bounds__(256) void k_gather64(const __half* __restrict__ xw,
                                                  __half* __restrict__ agg) {
    const int node = blockIdx.x * 32 + (threadIdx.x >> 3);
    if (node >= N_NODES) return;
    const int f   = (threadIdx.x & 7) << 3;
    int       i   = g_rowoff[node];
    const int end = g_rowoff[node + 1];
    float acc[8] = {0.f, 0.f, 0.f, 0.f, 0.f, 0.f, 0.f, 0.f};

    for (; i + 3 < end; i += 4) {
        const int s0 = __ldg(&g_csrc[i + 0]);
        const int s1 = __ldg(&g_csrc[i + 1]);
        const int s2 = __ldg(&g_csrc[i + 2]);
        const int s3 = __ldg(&g_csrc[i + 3]);
        const uint4 r0 = __ldg((const uint4*)&xw[(size_t)s0 * 64 + f]);
        const uint4 r1 = __ldg((const uint4*)&xw[(size_t)s1 * 64 + f]);
        const uint4 r2 = __ldg((const uint4*)&xw[(size_t)s2 * 64 + f]);
        const uint4 r3 = __ldg((const uint4*)&xw[(size_t)s3 * 64 + f]);
        h8_acc(acc, r0); h8_acc(acc, r1);
        h8_acc(acc, r2); h8_acc(acc, r3);
    }
    for (; i < end; i++) {
        const int s = __ldg(&g_csrc[i]);
        h8_acc(acc, __ldg((const uint4*)&xw[(size_t)s * 64 + f]));
    }

    union { uint4 u; __half2 h[4]; } o;
    o.h[0] = __floats2half2_rn(acc[0], acc[1]);
    o.h[1] = __floats2half2_rn(acc[2], acc[3]);
    o.h[2] = __floats2half2_rn(acc[4], acc[5]);
    o.h[3] = __floats2half2_rn(acc[6], acc[7]);
    *(uint4*)&agg[(size_t)node * 64 + f] = o.u;
}

// 40-wide fp16 gather with fused final epilogue (fp32 output)
__device__ __forceinline__ void h4_acc(float4& acc, uint2 raw) {
    union { uint2 u; __half2 h[2]; } p; p.u = raw;
    const float2 a = __half22float2(p.h[0]);
    const float2 b = __half22float2(p.h[1]);
    acc.x += a.x; acc.y += a.y; acc.z += b.x; acc.w += b.y;
}

__global__ __launch_bounds__(256) void k_gather40(const __half* __restrict__ xw,
                                                  float* __restrict__ out,
                                                  const float* __restrict__ b2) {
    const int node = blockIdx.x * 16 + (threadIdx.x >> 4);
    if (node >= N_NODES) return;
    const int f = (threadIdx.x & 15) << 2;
    if (f >= F_OUT) return;
    int       i   = g_rowoff[node];
    const int end = g_rowoff[node + 1];
    float4 acc = make_float4(0.f, 0.f, 0.f, 0.f);
    for (; i + 3 < end; i += 4) {
        const int s0 = __ldg(&g_csrc[i + 0]);
        const int s1 = __ldg(&g_csrc[i + 1]);
        const int s2 = __ldg(&g_csrc[i + 2]);
        const int s3 = __ldg(&g_csrc[i + 3]);
        h4_acc(acc, __ldg((const uint2*)&xw[(size_t)s0 * F_OUT + f]));
        h4_acc(acc, __ldg((const uint2*)&xw[(size_t)s1 * F_OUT + f]));
        h4_acc(acc, __ldg((const uint2*)&xw[(size_t)s2 * F_OUT + f]));
        h4_acc(acc, __ldg((const uint2*)&xw[(size_t)s3 * F_OUT + f]));
    }
    for (; i < end; i++) {
        const int s = __ldg(&g_csrc[i]);
        h4_acc(acc, __ldg((const uint2*)&xw[(size_t)s * F_OUT + f]));
    }
    const float nd = g_nd[node];
    float4 o;
    o.x = fmaf(acc.x, nd, __ldg(&b2[f + 0]));
    o.y = fmaf(acc.y, nd, __ldg(&b2[f + 1]));
    o.z = fmaf(acc.z, nd, __ldg(&b2[f + 2]));
    o.w = fmaf(acc.w, nd, __ldg(&b2[f + 3]));
    *(float4*)&out[(size_t)node * F_OUT + f] = o;
}

// ---------------- host launch ----------------
extern "C" void kernel_launch(void* const* d_in, const int* in_sizes, int n_in,
                              void* d_out, int out_size) {
    (void)in_sizes; (void)n_in; (void)out_size;
    const float* h   = (const float*)d_in[0];
    const float* W0  = (const float*)d_in[1];
    const float* b0  = (const float*)d_in[2];
    const float* W1  = (const float*)d_in[3];
    const float* b1  = (const float*)d_in[4];
    const float* W2  = (const float*)d_in[5];
    const float* b2  = (const float*)d_in[6];
    const int*   src = (const int*)d_in[7];
    const int*   dst = (const int*)d_in[8];
    float* out = (float*)d_out;

    __half *pXW64, *pXW40, *pAgg;
    cudaGetSymbolAddress((void**)&pXW64, g_xw64);
    cudaGetSymbolAddress((void**)&pXW40, g_xw40);
    cudaGetSymbolAddress((void**)&pAgg,  g_agg);

    static cudaStream_t s2 = []() {
        cudaStream_t s; cudaStreamCreateWithFlags(&s, cudaStreamNonBlocking); return s;
    }();
    static cudaEvent_t evFork = []() {
        cudaEvent_t e; cudaEventCreateWithFlags(&e, cudaEventDisableTiming); return e;
    }();
    static cudaEvent_t evJoin = []() {
        cudaEvent_t e; cudaEventCreateWithFlags(&e, cudaEventDisableTiming); return e;
    }();

    const int nodeBlocks   = (N_NODES + 255) / 256;
    const int edge4Blocks  = (N_EDGES / 4 + 255) / 256;
    const int gemmBlocks   = (N_NODES + 127) / 128;
    const int gath64Blocks = (N_NODES + 31) / 32;
    const int gath40Blocks = (N_NODES + 15) / 16;

    // ---- main: zero degrees, then fork ----
    k_zero_deg<<<(N_NODES / 4 + 255) / 256, 256>>>();
    cudaEventRecord(evFork, 0);

    // ---- side stream: src-degree -> ns -> GEMM0 (ns folded into epilogue) ----
    cudaStreamWaitEvent(s2, evFork, 0);
    k_deg_src<<<edge4Blocks, 256, 0, s2>>>(src);
    k_ns<<<nodeBlocks, 256, 0, s2>>>();
    k_gemm_mma<F_IN, F_HID, false, true><<<gemmBlocks, 256, 0, s2>>>(h, W0, pXW64, b0);
    cudaEventRecord(evJoin, s2);

    // ---- main: dst histogram + CSR ----
    k_deg_dst<<<edge4Blocks, 256>>>(dst);
    k_scan_block<<<SCAN_NB, SCAN_T>>>();
    k_finalize<<<SCAN_NB, SCAN_T>>>();
    k_fill<<<edge4Blocks, 256>>>(src, dst);

    // ---- join, then the serial back chain ----
    cudaStreamWaitEvent(0, evJoin, 0);
    k_gather64<<<gath64Blocks, 256>>>(pXW64, pAgg);

    k_gemm_mma<F_HID, F_HID, true, true><<<gemmBlocks, 256>>>(pAgg, W1, pXW64, b0);
    k_gather64<<<gath64Blocks, 256>>>(pXW64, pAgg);

    k_gemm_mma<F_HID, F_OUT, true, true><<<gemmBlocks, 256>>>(pAgg, W2, pXW40, b1);
    k_gather40<<<gath40Blocks, 256>>>(pXW40, out, b2);
}

// round 12
// speedup vs baseline: 1.1698x; 1.0871x over previous
#include <cuda_runtime.h>
#include <cuda_fp16.h>
#include <mma.h>
#include <cstdint>

using namespace nvcuda;

#define N_NODES 100000
#define N_EDGES 1600000
#define F_IN    128
#define F_HID   64
#define F_OUT   40

#define SCAN_T  1024
#define SCAN_NB ((N_NODES + SCAN_T - 1) / SCAN_T)   // 98

// ---------------- scratch (static device globals; no allocation) ----------------
__device__ int    g_degs_i[N_NODES];
__device__ int    g_degd_i[N_NODES];
__device__ float  g_ns[N_NODES];
__device__ float  g_nd[N_NODES];
__device__ int    g_incl[N_NODES];
__device__ int    g_rowoff[N_NODES + 1];
__device__ int    g_cursor[N_NODES];
__device__ int    g_partial[SCAN_NB];
__device__ int    g_csrc[N_EDGES];
__device__ __half g_hh  [(size_t)N_NODES * F_IN];    // fp16 copy of h
__device__ __half g_xw64[(size_t)N_NODES * F_HID];
__device__ __half g_xw40[(size_t)N_NODES * F_OUT];
__device__ __half g_agg [(size_t)N_NODES * F_HID];

// ---------------- h -> fp16 streaming convert (8 elems/thread) ----------------
__global__ void k_cvt_h(const float* __restrict__ h) {
    int i = blockIdx.x * blockDim.x + threadIdx.x;
    if (i < N_NODES * F_IN / 8) {
        const float4 a = __ldg(&((const float4*)h)[2 * i + 0]);
        const float4 b = __ldg(&((const float4*)h)[2 * i + 1]);
        union { uint4 u; __half2 x[4]; } o;
        o.x[0] = __floats2half2_rn(a.x, a.y);
        o.x[1] = __floats2half2_rn(a.z, a.w);
        o.x[2] = __floats2half2_rn(b.x, b.y);
        o.x[3] = __floats2half2_rn(b.z, b.w);
        ((uint4*)g_hh)[i] = o.u;
    }
}

// ---------------- zero both degree arrays (int4) ----------------
__global__ void k_zero_deg() {
    int i = blockIdx.x * blockDim.x + threadIdx.x;
    if (i < N_NODES / 4) {
        ((int4*)g_degs_i)[i] = make_int4(0, 0, 0, 0);
        ((int4*)g_degd_i)[i] = make_int4(0, 0, 0, 0);
    }
}

// ---------------- degree histograms (4 edges per thread) ----------------
__global__ void k_deg_dst(const int* __restrict__ dst) {
    int i = blockIdx.x * blockDim.x + threadIdx.x;
    if (i < N_EDGES / 4) {
        const int4 d = __ldg(&((const int4*)dst)[i]);
        atomicAdd(&g_degd_i[d.x], 1);
        atomicAdd(&g_degd_i[d.y], 1);
        atomicAdd(&g_degd_i[d.z], 1);
        atomicAdd(&g_degd_i[d.w], 1);
    }
}

__global__ void k_deg_src(const int* __restrict__ src) {
    int i = blockIdx.x * blockDim.x + threadIdx.x;
    if (i < N_EDGES / 4) {
        const int4 s = __ldg(&((const int4*)src)[i]);
        atomicAdd(&g_degs_i[s.x], 1);
        atomicAdd(&g_degs_i[s.y], 1);
        atomicAdd(&g_degs_i[s.z], 1);
        atomicAdd(&g_degs_i[s.w], 1);
    }
}

__global__ void k_ns() {
    int i = blockIdx.x * blockDim.x + threadIdx.x;
    if (i < N_NODES) g_ns[i] = rsqrtf(fmaxf((float)g_degs_i[i], 1.0f));
}

// ---------------- CSR build ----------------
__global__ __launch_bounds__(SCAN_T) void k_scan_block() {
    __shared__ int ws[32];
    int g = blockIdx.x * SCAN_T + threadIdx.x;
    int lane = threadIdx.x & 31, wid = threadIdx.x >> 5;
    int x = (g < N_NODES) ? g_degd_i[g] : 0;
#pragma unroll
    for (int o = 1; o < 32; o <<= 1) {
        int y = __shfl_up_sync(0xFFFFFFFFu, x, o);
        if (lane >= o) x += y;
    }
    if (lane == 31) ws[wid] = x;
    __syncthreads();
    if (wid == 0) {
        int y = ws[lane];
#pragma unroll
        for (int o = 1; o < 32; o <<= 1) {
            int z = __shfl_up_sync(0xFFFFFFFFu, y, o);
            if (lane >= o) y += z;
        }
        ws[lane] = y;
    }
    __syncthreads();
    int incl = x + (wid > 0 ? ws[wid - 1] : 0);
    if (g < N_NODES) g_incl[g] = incl;
    if (threadIdx.x == SCAN_T - 1) g_partial[blockIdx.x] = incl;
}

__global__ __launch_bounds__(SCAN_T) void k_finalize() {
    __shared__ int ws[32];
    __shared__ int s_off;
    const int tid = threadIdx.x;
    const int lane = tid & 31, w = tid >> 5;

    int v = 0;
    if (tid < SCAN_NB && tid < blockIdx.x) v = g_partial[tid];
#pragma unroll
    for (int o = 16; o > 0; o >>= 1) v += __shfl_down_sync(0xFFFFFFFFu, v, o);
    if (tid < 128 && lane == 0) ws[w] = v;
    __syncthreads();
    if (tid == 0) s_off = ws[0] + ws[1] + ws[2] + ws[3];
    __syncthreads();
    const int off = s_off;

    int g = blockIdx.x * SCAN_T + tid;
    if (g < N_NODES) {
        int dd   = g_degd_i[g];
        int incl = g_incl[g] + off;
        g_rowoff[g + 1] = incl;
        g_cursor[g] = incl - dd;
        if (g == 0) g_rowoff[0] = 0;
        g_nd[g] = rsqrtf(fmaxf((float)dd, 1.0f));
    }
}

__global__ void k_fill(const int* __restrict__ src, const int* __restrict__ dst) {
    int i = blockIdx.x * blockDim.x + threadIdx.x;
    if (i < N_EDGES / 4) {
        const int4 s = __ldg(&((const int4*)src)[i]);
        const int4 d = __ldg(&((const int4*)dst)[i]);
        g_csrc[atomicAdd(&g_cursor[d.x], 1)] = s.x;
        g_csrc[atomicAdd(&g_cursor[d.y], 1)] = s.y;
        g_csrc[atomicAdd(&g_cursor[d.z], 1)] = s.z;
        g_csrc[atomicAdd(&g_cursor[d.w], 1)] = s.w;
    }
}

// ---------------- HMMA GEMM, K-pipelined double buffer: Y = op(X)[fp16] @ W -> fp16 ----------------
// Block tile 128 rows x 64 cols, 8 warps (warp owns 16 rows x 64 cols).
// K processed in 64-wide chunks; chunk c+1 LDGs issued before chunk c's MMAs (reg prefetch).
// PRE: x' = relu(x * g_nd[row] + bpre[k]).  SNS: y = acc * g_ns[row].
template <int K, int M, bool PRE, bool SNS>
__global__ __launch_bounds__(256) void k_gemm_mma(const __half* __restrict__ X,
                                                  const float* __restrict__ W,
                                                  __half* __restrict__ Y,
                                                  const float* __restrict__ bpre) {
    static constexpr int KC = 64;
    static constexpr int NC = K / KC;
    static constexpr int AL = KC + 8;    // 72 halves, conflict-free for ldmatrix/STS
    static constexpr int BL = 72;
    static constexpr int A_HALVES = 128 * AL;
    static constexpr int AB_BYTES = 2 * A_HALVES * 2 + K * BL * 2;
    static constexpr int STAGE_BYTES = 8 * 16 * 64 * 4;
    static constexpr int SMEM_BYTES = AB_BYTES > STAGE_BYTES ? AB_BYTES : STAGE_BYTES;

    __shared__ __align__(16) char smem[SMEM_BYTES];
    __half* As0 = (__half*)smem;
    __half* As1 = (__half*)smem + A_HALVES;
    __half* Bs  = (__half*)smem + 2 * A_HALVES;
    float*  Cs  = (float*)smem;            // reused after last MMA sync

    const int tid  = threadIdx.x;
    const int warp = tid >> 5;
    const int lane = tid & 31;
    const int row0 = blockIdx.x * 128;

    // A role: 2 threads per row; each owns 32 consecutive halves of the 64-K chunk
    const int ar   = tid >> 1;
    const int ah   = (tid & 1) * 32;
    const int lrow = row0 + ar;
    const bool lok = (lrow < N_NODES);
    float ndv = 0.0f;
    if (PRE) ndv = lok ? g_nd[lrow] : 0.0f;

    // ---- B load: K x 64 cols fp32 W -> fp16 ----
#pragma unroll
    for (int i = 0; i < K / 16; i++) {
        const int q    = i * 256 + tid;
        const int brow = q >> 4;
        const int bcol = (q & 15) * 4;
        float4 wv = make_float4(0.f, 0.f, 0.f, 0.f);
        if (bcol < M)
            wv = *(const float4*)&W[(size_t)brow * M + bcol];
        union { uint2 u; __half2 h[2]; } p;
        p.h[0] = __floats2half2_rn(wv.x, wv.y);
        p.h[1] = __floats2half2_rn(wv.z, wv.w);
        *(uint2*)&Bs[brow * BL + bcol] = p.u;
    }

    uint4 raw[4] = {{0,0,0,0}, {0,0,0,0}, {0,0,0,0}, {0,0,0,0}};

    // prefetch + store chunk 0
    if (lok) {
#pragma unroll
        for (int u = 0; u < 4; u++)
            raw[u] = __ldg((const uint4*)&X[(size_t)lrow * K + ah + u * 8]);
    }
    {
        __half* Ad = As0;
#pragma unroll
        for (int u = 0; u < 4; u++) {
            union { uint4 q; __half2 h[4]; } in; in.q = raw[u];
            if (PRE) {
                union { uint4 q; __half2 h[4]; } o;
#pragma unroll
                for (int j = 0; j < 4; j++) {
                    const float2 v = __half22float2(in.h[j]);
                    const int k = ah + u * 8 + 2 * j;
                    o.h[j] = __floats2half2_rn(
                        fmaxf(fmaf(v.x, ndv, __ldg(&bpre[k + 0])), 0.f),
                        fmaxf(fmaf(v.y, ndv, __ldg(&bpre[k + 1])), 0.f));
                }
                *(uint4*)&Ad[ar * AL + ah + u * 8] = o.q;
            } else {
                *(uint4*)&Ad[ar * AL + ah + u * 8] = in.q;
            }
        }
    }
    __syncthreads();

    wmma::fragment<wmma::accumulator, 16, 16, 16, float> cf[4];
#pragma unroll
    for (int n = 0; n < 4; n++) wmma::fill_fragment(cf[n], 0.0f);

#pragma unroll
    for (int c = 0; c < NC; c++) {
        // prefetch next chunk (loads in flight during this chunk's MMAs)
        if (c + 1 < NC && lok) {
#pragma unroll
            for (int u = 0; u < 4; u++)
                raw[u] = __ldg((const uint4*)&X[(size_t)lrow * K + (c + 1) * KC + ah + u * 8]);
        }

        const __half* Ac = (c & 1) ? As1 : As0;
#pragma unroll
        for (int kc = 0; kc < KC; kc += 16) {
            wmma::fragment<wmma::matrix_a, 16, 16, 16, __half, wmma::row_major> af;
            wmma::load_matrix_sync(af, &Ac[(warp * 16) * AL + kc], AL);
#pragma unroll
            for (int n = 0; n < 4; n++) {
                wmma::fragment<wmma::matrix_b, 16, 16, 16, __half, wmma::row_major> bf;
                wmma::load_matrix_sync(bf, &Bs[(c * KC + kc) * BL + n * 16], BL);
                wmma::mma_sync(cf[n], af, bf, cf[n]);
            }
        }

        if (c + 1 < NC) {
            __half* Ad = ((c + 1) & 1) ? As1 : As0;
#pragma unroll
            for (int u = 0; u < 4; u++) {
                union { uint4 q; __half2 h[4]; } in; in.q = raw[u];
                if (PRE) {
                    union { uint4 q; __half2 h[4]; } o;
#pragma unroll
                    for (int j = 0; j < 4; j++) {
                        const float2 v = __half22float2(in.h[j]);
                        const int k = (c + 1) * KC + ah + u * 8 + 2 * j;
                        o.h[j] = __floats2half2_rn(
                            fmaxf(fmaf(v.x, ndv, __ldg(&bpre[k + 0])), 0.f),
                            fmaxf(fmaf(v.y, ndv, __ldg(&bpre[k + 1])), 0.f));
                    }
                    *(uint4*)&Ad[ar * AL + ah + u * 8] = o.q;
                } else {
                    *(uint4*)&Ad[ar * AL + ah + u * 8] = in.q;
                }
            }
            __syncthreads();
        }
    }
    __syncthreads();   // A/B smem dead; reuse as fp32 staging

    // ---- epilogue: stage fp32, scale by ns, convert fp16, store ----
    float* cwarp = Cs + warp * (16 * 64);
#pragma unroll
    for (int n = 0; n < 4; n++)
        wmma::store_matrix_sync(cwarp + n * 16, cf[n], 64, wmma::mem_row_major);
    __syncwarp();

    for (int q = lane; q < 256; q += 32) {
        const int r  = q >> 4;
        const int qc = (q & 15) * 4;
        const int rr = row0 + warp * 16 + r;
        if (rr < N_NODES && qc < M) {
            const float s = SNS ? g_ns[rr] : 1.0f;
            union { uint2 u; __half2 h[2]; } p;
            p.h[0] = __floats2half2_rn(cwarp[r * 64 + qc + 0] * s, cwarp[r * 64 + qc + 1] * s);
            p.h[1] = __floats2half2_rn(cwarp[r * 64 + qc + 2] * s, cwarp[r * 64 + qc + 3] * s);
            *(uint2*)&Y[(size_t)rr * M + qc] = p.u;
        }
    }
}

// ---------------- CSR gather (fp16 in/out, fp32 accum): 8 thr/node, 16B loads ----------------
__device__ __forceinline__ void h8_acc(float* acc, uint4 raw) {
    union { uint4 u; __half2 h[4]; } p; p.u = raw;
#pragma unroll
    for (int j = 0; j < 4; j++) {
        const float2 v = __half22float2(p.h[j]);
        acc[2 * j + 0] += v.x;
        acc[2 * j + 1] += v.y;
    }
}

__global__ __launch_bounds__(256) void k_gather64(const __half* __restrict__ xw,
                                                  __half* __restrict__ agg) {
    const int node = blockIdx.x * 32 + (threadIdx.x >> 3);
    if (node >= N_NODES) return;
    const int f   = (threadIdx.x & 7) << 3;
    int       i   = g_rowoff[node];
    const int end = g_rowoff[node + 1];
    float acc[8] = {0.f, 0.f, 0.f, 0.f, 0.f, 0.f, 0.f, 0.f};

    for (; i + 3 < end; i += 4) {
        const int s0 = __ldg(&g_csrc[i + 0]);
        const int s1 = __ldg(&g_csrc[i + 1]);
        const int s2 = __ldg(&g_csrc[i + 2]);
        const int s3 = __ldg(&g_csrc[i + 3]);
        const uint4 r0 = __ldg((const uint4*)&xw[(size_t)s0 * 64 + f]);
        const uint4 r1 = __ldg((const uint4*)&xw[(size_t)s1 * 64 + f]);
        const uint4 r2 = __ldg((const uint4*)&xw[(size_t)s2 * 64 + f]);
        const uint4 r3 = __ldg((const uint4*)&xw[(size_t)s3 * 64 + f]);
        h8_acc(acc, r0); h8_acc(acc, r1);
        h8_acc(acc, r2); h8_acc(acc, r3);
    }
    for (; i < end; i++) {
        const int s = __ldg(&g_csrc[i]);
        h8_acc(acc, __ldg((const uint4*)&xw[(size_t)s * 64 + f]));
    }

    union { uint4 u; __half2 h[4]; } o;
    o.h[0] = __floats2half2_rn(acc[0], acc[1]);
    o.h[1] = __floats2half2_rn(acc[2], acc[3]);
    o.h[2] = __floats2half2_rn(acc[4], acc[5]);
    o.h[3] = __floats2half2_rn(acc[6], acc[7]);
    *(uint4*)&agg[(size_t)node * 64 + f] = o.u;
}

// 40-wide fp16 gather with fused final epilogue (fp32 output)
__device__ __forceinline__ void h4_acc(float4& acc, uint2 raw) {
    union { uint2 u; __half2 h[2]; } p; p.u = raw;
    const float2 a = __half22float2(p.h[0]);
    const float2 b = __half22float2(p.h[1]);
    acc.x += a.x; acc.y += a.y; acc.z += b.x; acc.w += b.y;
}

__global__ __launch_bounds__(256) void k_gather40(const __half* __restrict__ xw,
                                                  float* __restrict__ out,
                                                  const float* __restrict__ b2) {
    const int node = blockIdx.x * 16 + (threadIdx.x >> 4);
    if (node >= N_NODES) return;
    const int f = (threadIdx.x & 15) << 2;
    if (f >= F_OUT) return;
    int       i   = g_rowoff[node];
    const int end = g_rowoff[node + 1];
    float4 acc = make_float4(0.f, 0.f, 0.f, 0.f);
    for (; i + 3 < end; i += 4) {
        const int s0 = __ldg(&g_csrc[i + 0]);
        const int s1 = __ldg(&g_csrc[i + 1]);
        const int s2 = __ldg(&g_csrc[i + 2]);
        const int s3 = __ldg(&g_csrc[i + 3]);
        h4_acc(acc, __ldg((const uint2*)&xw[(size_t)s0 * F_OUT + f]));
        h4_acc(acc, __ldg((const uint2*)&xw[(size_t)s1 * F_OUT + f]));
        h4_acc(acc, __ldg((const uint2*)&xw[(size_t)s2 * F_OUT + f]));
        h4_acc(acc, __ldg((const uint2*)&xw[(size_t)s3 * F_OUT + f]));
    }
    for (; i < end; i++) {
        const int s = __ldg(&g_csrc[i]);
        h4_acc(acc, __ldg((const uint2*)&xw[(size_t)s * F_OUT + f]));
    }
    const float nd = g_nd[node];
    float4 o;
    o.x = fmaf(acc.x, nd, __ldg(&b2[f + 0]));
    o.y = fmaf(acc.y, nd, __ldg(&b2[f + 1]));
    o.z = fmaf(acc.z, nd, __ldg(&b2[f + 2]));
    o.w = fmaf(acc.w, nd, __ldg(&b2[f + 3]));
    *(float4*)&out[(size_t)node * F_OUT + f] = o;
}

// ---------------- host launch ----------------
extern "C" void kernel_launch(void* const* d_in, const int* in_sizes, int n_in,
                              void* d_out, int out_size) {
    (void)in_sizes; (void)n_in; (void)out_size;
    const float* h   = (const float*)d_in[0];
    const float* W0  = (const float*)d_in[1];
    const float* b0  = (const float*)d_in[2];
    const float* W1  = (const float*)d_in[3];
    const float* b1  = (const float*)d_in[4];
    const float* W2  = (const float*)d_in[5];
    const float* b2  = (const float*)d_in[6];
    const int*   src = (const int*)d_in[7];
    const int*   dst = (const int*)d_in[8];
    float* out = (float*)d_out;

    __half *pHH, *pXW64, *pXW40, *pAgg;
    cudaGetSymbolAddress((void**)&pHH,   g_hh);
    cudaGetSymbolAddress((void**)&pXW64, g_xw64);
    cudaGetSymbolAddress((void**)&pXW40, g_xw40);
    cudaGetSymbolAddress((void**)&pAgg,  g_agg);

    static cudaStream_t s2 = []() {
        cudaStream_t s; cudaStreamCreateWithFlags(&s, cudaStreamNonBlocking); return s;
    }();
    auto mkev = []() {
        cudaEvent_t e; cudaEventCreateWithFlags(&e, cudaEventDisableTiming); return e;
    };
    static cudaEvent_t evF0   = mkev();
    static cudaEvent_t evZero = mkev();
    static cudaEvent_t evJoin = mkev();

    const int nodeBlocks   = (N_NODES + 255) / 256;
    const int edge4Blocks  = (N_EDGES / 4 + 255) / 256;
    const int cvtBlocks    = (N_NODES * F_IN / 8 + 255) / 256;
    const int gemmBlocks   = (N_NODES + 127) / 128;
    const int gath64Blocks = (N_NODES + 31) / 32;
    const int gath40Blocks = (N_NODES + 15) / 16;

    // ---- main: fork immediately (cvt has no deps), then zero degrees ----
    cudaEventRecord(evF0, 0);
    k_zero_deg<<<(N_NODES / 4 + 255) / 256, 256>>>();
    cudaEventRecord(evZero, 0);

    // ---- side stream: h->fp16, then src-degree -> ns -> GEMM0 ----
    cudaStreamWaitEvent(s2, evF0, 0);
    k_cvt_h<<<cvtBlocks, 256, 0, s2>>>(h);
    cudaStreamWaitEvent(s2, evZero, 0);
    k_deg_src<<<edge4Blocks, 256, 0, s2>>>(src);
    k_ns<<<nodeBlocks, 256, 0, s2>>>();
    k_gemm_mma<F_IN, F_HID, false, true><<<gemmBlocks, 256, 0, s2>>>(pHH, W0, pXW64, b0);
    cudaEventRecord(evJoin, s2);

    // ---- main: dst histogram + CSR ----
    k_deg_dst<<<edge4Blocks, 256>>>(dst);
    k_scan_block<<<SCAN_NB, SCAN_T>>>();
    k_finalize<<<SCAN_NB, SCAN_T>>>();
    k_fill<<<edge4Blocks, 256>>>(src, dst);

    // ---- join, then the serial back chain ----
    cudaStreamWaitEvent(0, evJoin, 0);
    k_gather64<<<gath64Blocks, 256>>>(pXW64, pAgg);

    k_gemm_mma<F_HID, F_HID, true, true><<<gemmBlocks, 256>>>(pAgg, W1, pXW64, b0);
    k_gather64<<<gath64Blocks, 256>>>(pXW64, pAgg);

    k_gemm_mma<F_HID, F_OUT, true, true><<<gemmBlocks, 256>>>(pAgg, W2, pXW40, b1);
    k_gather40<<<gath40Blocks, 256>>>(pXW40, out, b2);
}

// round 13
// speedup vs baseline: 1.1866x; 1.0144x over previous
#include <cuda_runtime.h>
#include <cuda_fp16.h>
#include <mma.h>
#include <cstdint>

using namespace nvcuda;

#define N_NODES 100000
#define N_EDGES 1600000
#define F_IN    128
#define F_HID   64
#define F_OUT   40

#define SCAN_T  1024
#define SCAN_NB ((N_NODES + SCAN_T - 1) / SCAN_T)   // 98

// ---------------- scratch (static device globals; no allocation) ----------------
__device__ int    g_degs_i[N_NODES];
__device__ int    g_degd_i[N_NODES];
__device__ float  g_ns[N_NODES];
__device__ float  g_nd[N_NODES];
__device__ int    g_incl[N_NODES];
__device__ int    g_rowoff[N_NODES + 1];
__device__ int    g_partial[SCAN_NB];
__device__ int    g_pos[N_EDGES];                    // per-edge slot within its dst row
__device__ int    g_csrc[N_EDGES];
__device__ __half g_hh  [(size_t)N_NODES * F_IN];    // fp16 copy of h
__device__ __half g_xw64[(size_t)N_NODES * F_HID];
__device__ __half g_xw40[(size_t)N_NODES * F_OUT];
__device__ __half g_agg [(size_t)N_NODES * F_HID];

// ---------------- h -> fp16 streaming convert (8 elems/thread) ----------------
__global__ void k_cvt_h(const float* __restrict__ h) {
    int i = blockIdx.x * blockDim.x + threadIdx.x;
    if (i < N_NODES * F_IN / 8) {
        const float4 a = __ldg(&((const float4*)h)[2 * i + 0]);
        const float4 b = __ldg(&((const float4*)h)[2 * i + 1]);
        union { uint4 u; __half2 x[4]; } o;
        o.x[0] = __floats2half2_rn(a.x, a.y);
        o.x[1] = __floats2half2_rn(a.z, a.w);
        o.x[2] = __floats2half2_rn(b.x, b.y);
        o.x[3] = __floats2half2_rn(b.z, b.w);
        ((uint4*)g_hh)[i] = o.u;
    }
}

// ---------------- per-stream degree zeroing (int4) ----------------
__global__ void k_zero_degd() {
    int i = blockIdx.x * blockDim.x + threadIdx.x;
    if (i < N_NODES / 4) ((int4*)g_degd_i)[i] = make_int4(0, 0, 0, 0);
}
__global__ void k_zero_degs() {
    int i = blockIdx.x * blockDim.x + threadIdx.x;
    if (i < N_NODES / 4) ((int4*)g_degs_i)[i] = make_int4(0, 0, 0, 0);
}

// ---------------- dst histogram + per-edge position capture ----------------
__global__ void k_deg_dst_pos(const int* __restrict__ dst) {
    int i = blockIdx.x * blockDim.x + threadIdx.x;
    if (i < N_EDGES / 4) {
        const int4 d = __ldg(&((const int4*)dst)[i]);
        int4 p;
        p.x = atomicAdd(&g_degd_i[d.x], 1);
        p.y = atomicAdd(&g_degd_i[d.y], 1);
        p.z = atomicAdd(&g_degd_i[d.z], 1);
        p.w = atomicAdd(&g_degd_i[d.w], 1);
        ((int4*)g_pos)[i] = p;
    }
}

__global__ void k_deg_src(const int* __restrict__ src) {
    int i = blockIdx.x * blockDim.x + threadIdx.x;
    if (i < N_EDGES / 4) {
        const int4 s = __ldg(&((const int4*)src)[i]);
        atomicAdd(&g_degs_i[s.x], 1);
        atomicAdd(&g_degs_i[s.y], 1);
        atomicAdd(&g_degs_i[s.z], 1);
        atomicAdd(&g_degs_i[s.w], 1);
    }
}

__global__ void k_ns() {
    int i = blockIdx.x * blockDim.x + threadIdx.x;
    if (i < N_NODES) g_ns[i] = rsqrtf(fmaxf((float)g_degs_i[i], 1.0f));
}

// ---------------- CSR build ----------------
__global__ __launch_bounds__(SCAN_T) void k_scan_block() {
    __shared__ int ws[32];
    int g = blockIdx.x * SCAN_T + threadIdx.x;
    int lane = threadIdx.x & 31, wid = threadIdx.x >> 5;
    int x = (g < N_NODES) ? g_degd_i[g] : 0;
#pragma unroll
    for (int o = 1; o < 32; o <<= 1) {
        int y = __shfl_up_sync(0xFFFFFFFFu, x, o);
        if (lane >= o) x += y;
    }
    if (lane == 31) ws[wid] = x;
    __syncthreads();
    if (wid == 0) {
        int y = ws[lane];
#pragma unroll
        for (int o = 1; o < 32; o <<= 1) {
            int z = __shfl_up_sync(0xFFFFFFFFu, y, o);
            if (lane >= o) y += z;
        }
        ws[lane] = y;
    }
    __syncthreads();
    int incl = x + (wid > 0 ? ws[wid - 1] : 0);
    if (g < N_NODES) g_incl[g] = incl;
    if (threadIdx.x == SCAN_T - 1) g_partial[blockIdx.x] = incl;
}

// finalize rowoff (exclusive) + nd norm; no cursor needed anymore
__global__ __launch_bounds__(SCAN_T) void k_finalize() {
    __shared__ int ws[32];
    __shared__ int s_off;
    const int tid = threadIdx.x;
    const int lane = tid & 31, w = tid >> 5;

    int v = 0;
    if (tid < SCAN_NB && tid < blockIdx.x) v = g_partial[tid];
#pragma unroll
    for (int o = 16; o > 0; o >>= 1) v += __shfl_down_sync(0xFFFFFFFFu, v, o);
    if (tid < 128 && lane == 0) ws[w] = v;
    __syncthreads();
    if (tid == 0) s_off = ws[0] + ws[1] + ws[2] + ws[3];
    __syncthreads();
    const int off = s_off;

    int g = blockIdx.x * SCAN_T + tid;
    if (g < N_NODES) {
        int dd   = g_degd_i[g];
        int incl = g_incl[g] + off;
        g_rowoff[g + 1] = incl;
        if (g == 0) g_rowoff[0] = 0;
        g_nd[g] = rsqrtf(fmaxf((float)dd, 1.0f));
    }
}

// atomic-free fill: slot = rowoff[dst] + pos[e]
__global__ void k_fill(const int* __restrict__ src, const int* __restrict__ dst) {
    int i = blockIdx.x * blockDim.x + threadIdx.x;
    if (i < N_EDGES / 4) {
        const int4 s = __ldg(&((const int4*)src)[i]);
        const int4 d = __ldg(&((const int4*)dst)[i]);
        const int4 p = __ldg(&((const int4*)g_pos)[i]);
        g_csrc[__ldg(&g_rowoff[d.x]) + p.x] = s.x;
        g_csrc[__ldg(&g_rowoff[d.y]) + p.y] = s.y;
        g_csrc[__ldg(&g_rowoff[d.z]) + p.z] = s.z;
        g_csrc[__ldg(&g_rowoff[d.w]) + p.w] = s.w;
    }
}

// ---------------- HMMA GEMM, K-pipelined double buffer: Y = op(X)[fp16] @ W -> fp16 ----------------
// Block tile 128 rows x 64 cols, 8 warps (warp owns 16 rows x 64 cols).
// PRE: x' = relu(x * g_nd[row] + bpre[k]).  SNS: y = acc * g_ns[row].
template <int K, int M, bool PRE, bool SNS>
__global__ __launch_bounds__(256) void k_gemm_mma(const __half* __restrict__ X,
                                                  const float* __restrict__ W,
                                                  __half* __restrict__ Y,
                                                  const float* __restrict__ bpre) {
    static constexpr int KC = 64;
    static constexpr int NC = K / KC;
    static constexpr int AL = KC + 8;    // 72 halves
    static constexpr int BL = 72;
    static constexpr int A_HALVES = 128 * AL;
    static constexpr int AB_BYTES = 2 * A_HALVES * 2 + K * BL * 2;
    static constexpr int STAGE_BYTES = 8 * 16 * 64 * 4;
    static constexpr int SMEM_BYTES = AB_BYTES > STAGE_BYTES ? AB_BYTES : STAGE_BYTES;

    __shared__ __align__(16) char smem[SMEM_BYTES];
    __half* As0 = (__half*)smem;
    __half* As1 = (__half*)smem + A_HALVES;
    __half* Bs  = (__half*)smem + 2 * A_HALVES;
    float*  Cs  = (float*)smem;            // reused after last MMA sync

    const int tid  = threadIdx.x;
    const int warp = tid >> 5;
    const int lane = tid & 31;
    const int row0 = blockIdx.x * 128;

    const int ar   = tid >> 1;
    const int ah   = (tid & 1) * 32;
    const int lrow = row0 + ar;
    const bool lok = (lrow < N_NODES);
    float ndv = 0.0f;
    if (PRE) ndv = lok ? g_nd[lrow] : 0.0f;

    // ---- B load: K x 64 cols fp32 W -> fp16 ----
#pragma unroll
    for (int i = 0; i < K / 16; i++) {
        const int q    = i * 256 + tid;
        const int brow = q >> 4;
        const int bcol = (q & 15) * 4;
        float4 wv = make_float4(0.f, 0.f, 0.f, 0.f);
        if (bcol < M)
            wv = *(const float4*)&W[(size_t)brow * M + bcol];
        union { uint2 u; __half2 h[2]; } p;
        p.h[0] = __floats2half2_rn(wv.x, wv.y);
        p.h[1] = __floats2half2_rn(wv.z, wv.w);
        *(uint2*)&Bs[brow * BL + bcol] = p.u;
    }

    uint4 raw[4] = {{0,0,0,0}, {0,0,0,0}, {0,0,0,0}, {0,0,0,0}};

    if (lok) {
#pragma unroll
        for (int u = 0; u < 4; u++)
            raw[u] = __ldg((const uint4*)&X[(size_t)lrow * K + ah + u * 8]);
    }
    {
        __half* Ad = As0;
#pragma unroll
        for (int u = 0; u < 4; u++) {
            union { uint4 q; __half2 h[4]; } in; in.q = raw[u];
            if (PRE) {
                union { uint4 q; __half2 h[4]; } o;
#pragma unroll
                for (int j = 0; j < 4; j++) {
                    const float2 v = __half22float2(in.h[j]);
                    const int k = ah + u * 8 + 2 * j;
                    o.h[j] = __floats2half2_rn(
                        fmaxf(fmaf(v.x, ndv, __ldg(&bpre[k + 0])), 0.f),
                        fmaxf(fmaf(v.y, ndv, __ldg(&bpre[k + 1])), 0.f));
                }
                *(uint4*)&Ad[ar * AL + ah + u * 8] = o.q;
            } else {
                *(uint4*)&Ad[ar * AL + ah + u * 8] = in.q;
            }
        }
    }
    __syncthreads();

    wmma::fragment<wmma::accumulator, 16, 16, 16, float> cf[4];
#pragma unroll
    for (int n = 0; n < 4; n++) wmma::fill_fragment(cf[n], 0.0f);

#pragma unroll
    for (int c = 0; c < NC; c++) {
        if (c + 1 < NC && lok) {
#pragma unroll
            for (int u = 0; u < 4; u++)
                raw[u] = __ldg((const uint4*)&X[(size_t)lrow * K + (c + 1) * KC + ah + u * 8]);
        }

        const __half* Ac = (c & 1) ? As1 : As0;
#pragma unroll
        for (int kc = 0; kc < KC; kc += 16) {
            wmma::fragment<wmma::matrix_a, 16, 16, 16, __half, wmma::row_major> af;
            wmma::load_matrix_sync(af, &Ac[(warp * 16) * AL + kc], AL);
#pragma unroll
            for (int n = 0; n < 4; n++) {
                wmma::fragment<wmma::matrix_b, 16, 16, 16, __half, wmma::row_major> bf;
                wmma::load_matrix_sync(bf, &Bs[(c * KC + kc) * BL + n * 16], BL);
                wmma::mma_sync(cf[n], af, bf, cf[n]);
            }
        }

        if (c + 1 < NC) {
            __half* Ad = ((c + 1) & 1) ? As1 : As0;
#pragma unroll
            for (int u = 0; u < 4; u++) {
                union { uint4 q; __half2 h[4]; } in; in.q = raw[u];
                if (PRE) {
                    union { uint4 q; __half2 h[4]; } o;
#pragma unroll
                    for (int j = 0; j < 4; j++) {
                        const float2 v = __half22float2(in.h[j]);
                        const int k = (c + 1) * KC + ah + u * 8 + 2 * j;
                        o.h[j] = __floats2half2_rn(
                            fmaxf(fmaf(v.x, ndv, __ldg(&bpre[k + 0])), 0.f),
                            fmaxf(fmaf(v.y, ndv, __ldg(&bpre[k + 1])), 0.f));
                    }
                    *(uint4*)&Ad[ar * AL + ah + u * 8] = o.q;
                } else {
                    *(uint4*)&Ad[ar * AL + ah + u * 8] = in.q;
                }
            }
            __syncthreads();
        }
    }
    __syncthreads();   // A/B smem dead; reuse as fp32 staging

    float* cwarp = Cs + warp * (16 * 64);
#pragma unroll
    for (int n = 0; n < 4; n++)
        wmma::store_matrix_sync(cwarp + n * 16, cf[n], 64, wmma::mem_row_major);
    __syncwarp();

    for (int q = lane; q < 256; q += 32) {
        const int r  = q >> 4;
        const int qc = (q & 15) * 4;
        const int rr = row0 + warp * 16 + r;
        if (rr < N_NODES && qc < M) {
            const float s = SNS ? g_ns[rr] : 1.0f;
            union { uint2 u; __half2 h[2]; } p;
            p.h[0] = __floats2half2_rn(cwarp[r * 64 + qc + 0] * s, cwarp[r * 64 + qc + 1] * s);
            p.h[1] = __floats2half2_rn(cwarp[r * 64 + qc + 2] * s, cwarp[r * 64 + qc + 3] * s);
            *(uint2*)&Y[(size_t)rr * M + qc] = p.u;
        }
    }
}

// ---------------- CSR gather (fp16 in/out, fp32 accum): 8 thr/node, 16B loads ----------------
__device__ __forceinline__ void h8_acc(float* acc, uint4 raw) {
    union { uint4 u; __half2 h[4]; } p; p.u = raw;
#pragma unroll
    for (int j = 0; j < 4; j++) {
        const float2 v = __half22float2(p.h[j]);
        acc[2 * j + 0] += v.x;
        acc[2 * j + 1] += v.y;
    }
}

__global__ __launch_bounds__(256) void k_gather64(const __half* __restrict__ xw,
                                                  __half* __restrict__ agg) {
    const int node = blockIdx.x * 32 + (threadIdx.x >> 3);
    if (node >= N_NODES) return;
    const int f   = (threadIdx.x & 7) << 3;
    int       i   = g_rowoff[node];
    const int end = g_rowoff[node + 1];
    float acc[8] = {0.f, 0.f, 0.f, 0.f, 0.f, 0.f, 0.f, 0.f};

    for (; i + 3 < end; i += 4) {
        const int s0 = __ldg(&g_csrc[i + 0]);
        const int s1 = __ldg(&g_csrc[i + 1]);
        const int s2 = __ldg(&g_csrc[i + 2]);
        const int s3 = __ldg(&g_csrc[i + 3]);
        const uint4 r0 = __ldg((const uint4*)&xw[(size_t)s0 * 64 + f]);
        const uint4 r1 = __ldg((const uint4*)&xw[(size_t)s1 * 64 + f]);
        const uint4 r2 = __ldg((const uint4*)&xw[(size_t)s2 * 64 + f]);
        const uint4 r3 = __ldg((const uint4*)&xw[(size_t)s3 * 64 + f]);
        h8_acc(acc, r0); h8_acc(acc, r1);
        h8_acc(acc, r2); h8_acc(acc, r3);
    }
    for (; i < end; i++) {
        const int s = __ldg(&g_csrc[i]);
        h8_acc(acc, __ldg((const uint4*)&xw[(size_t)s * 64 + f]));
    }

    union { uint4 u; __half2 h[4]; } o;
    o.h[0] = __floats2half2_rn(acc[0], acc[1]);
    o.h[1] = __floats2half2_rn(acc[2], acc[3]);
    o.h[2] = __floats2half2_rn(acc[4], acc[5]);
    o.h[3] = __floats2half2_rn(acc[6], acc[7]);
    *(uint4*)&agg[(size_t)node * 64 + f] = o.u;
}

// 40-wide fp16 gather with fused final epilogue (fp32 output)
__device__ __forceinline__ void h4_acc(float4& acc, uint2 raw) {
    union { uint2 u; __half2 h[2]; } p; p.u = raw;
    const float2 a = __half22float2(p.h[0]);
    const float2 b = __half22float2(p.h[1]);
    acc.x += a.x; acc.y += a.y; acc.z += b.x; acc.w += b.y;
}

__global__ __launch_bounds__(256) void k_gather40(const __half* __restrict__ xw,
                                                  float* __restrict__ out,
                                                  const float* __restrict__ b2) {
    const int node = blockIdx.x * 16 + (threadIdx.x >> 4);
    if (node >= N_NODES) return;
    const int f = (threadIdx.x & 15) << 2;
    if (f >= F_OUT) return;
    int       i   = g_rowoff[node];
    const int end = g_rowoff[node + 1];
    float4 acc = make_float4(0.f, 0.f, 0.f, 0.f);
    for (; i + 3 < end; i += 4) {
        const int s0 = __ldg(&g_csrc[i + 0]);
        const int s1 = __ldg(&g_csrc[i + 1]);
        const int s2 = __ldg(&g_csrc[i + 2]);
        const int s3 = __ldg(&g_csrc[i + 3]);
        h4_acc(acc, __ldg((const uint2*)&xw[(size_t)s0 * F_OUT + f]));
        h4_acc(acc, __ldg((const uint2*)&xw[(size_t)s1 * F_OUT + f]));
        h4_acc(acc, __ldg((const uint2*)&xw[(size_t)s2 * F_OUT + f]));
        h4_acc(acc, __ldg((const uint2*)&xw[(size_t)s3 * F_OUT + f]));
    }
    for (; i < end; i++) {
        const int s = __ldg(&g_csrc[i]);
        h4_acc(acc, __ldg((const uint2*)&xw[(size_t)s * F_OUT + f]));
    }
    const float nd = g_nd[node];
    float4 o;
    o.x = fmaf(acc.x, nd, __ldg(&b2[f + 0]));
    o.y = fmaf(acc.y, nd, __ldg(&b2[f + 1]));
    o.z = fmaf(acc.z, nd, __ldg(&b2[f + 2]));
    o.w = fmaf(acc.w, nd, __ldg(&b2[f + 3]));
    *(float4*)&out[(size_t)node * F_OUT + f] = o;
}

// ---------------- host launch ----------------
extern "C" void kernel_launch(void* const* d_in, const int* in_sizes, int n_in,
                              void* d_out, int out_size) {
    (void)in_sizes; (void)n_in; (void)out_size;
    const float* h   = (const float*)d_in[0];
    const float* W0  = (const float*)d_in[1];
    const float* b0  = (const float*)d_in[2];
    const float* W1  = (const float*)d_in[3];
    const float* b1  = (const float*)d_in[4];
    const float* W2  = (const float*)d_in[5];
    const float* b2  = (const float*)d_in[6];
    const int*   src = (const int*)d_in[7];
    const int*   dst = (const int*)d_in[8];
    float* out = (float*)d_out;

    __half *pHH, *pXW64, *pXW40, *pAgg;
    cudaGetSymbolAddress((void**)&pHH,   g_hh);
    cudaGetSymbolAddress((void**)&pXW64, g_xw64);
    cudaGetSymbolAddress((void**)&pXW40, g_xw40);
    cudaGetSymbolAddress((void**)&pAgg,  g_agg);

    static cudaStream_t s2 = []() {
        cudaStream_t s; cudaStreamCreateWithFlags(&s, cudaStreamNonBlocking); return s;
    }();
    auto mkev = []() {
        cudaEvent_t e; cudaEventCreateWithFlags(&e, cudaEventDisableTiming); return e;
    };
    static cudaEvent_t evF0   = mkev();
    static cudaEvent_t evJoin = mkev();

    const int nodeBlocks   = (N_NODES + 255) / 256;
    const int node4Blocks  = (N_NODES / 4 + 255) / 256;
    const int edge4Blocks  = (N_EDGES / 4 + 255) / 256;
    const int cvtBlocks    = (N_NODES * F_IN / 8 + 255) / 256;
    const int gemmBlocks   = (N_NODES + 127) / 128;
    const int gath64Blocks = (N_NODES + 31) / 32;
    const int gath40Blocks = (N_NODES + 15) / 16;

    // ---- fork immediately; each stream zeroes its own degree array ----
    cudaEventRecord(evF0, 0);

    // ---- side stream: h->fp16, zero degs, src-degree -> ns -> GEMM0 ----
    cudaStreamWaitEvent(s2, evF0, 0);
    k_cvt_h<<<cvtBlocks, 256, 0, s2>>>(h);
    k_zero_degs<<<node4Blocks, 256, 0, s2>>>();
    k_deg_src<<<edge4Blocks, 256, 0, s2>>>(src);
    k_ns<<<nodeBlocks, 256, 0, s2>>>();
    k_gemm_mma<F_IN, F_HID, false, true><<<gemmBlocks, 256, 0, s2>>>(pHH, W0, pXW64, b0);
    cudaEventRecord(evJoin, s2);

    // ---- main: zero degd, dst histogram (+pos), scan, finalize, atomic-free fill ----
    k_zero_degd<<<node4Blocks, 256>>>();
    k_deg_dst_pos<<<edge4Blocks, 256>>>(dst);
    k_scan_block<<<SCAN_NB, SCAN_T>>>();
    k_finalize<<<SCAN_NB, SCAN_T>>>();
    k_fill<<<edge4Blocks, 256>>>(src, dst);

    // ---- join, then the serial back chain ----
    cudaStreamWaitEvent(0, evJoin, 0);
    k_gather64<<<gath64Blocks, 256>>>(pXW64, pAgg);

    k_gemm_mma<F_HID, F_HID, true, true><<<gemmBlocks, 256>>>(pAgg, W1, pXW64, b0);
    k_gather64<<<gath64Blocks, 256>>>(pXW64, pAgg);

    k_gemm_mma<F_HID, F_OUT, true, true><<<gemmBlocks, 256>>>(pAgg, W2, pXW40, b1);
    k_gather40<<<gath40Blocks, 256>>>(pXW40, out, b2);
}